// round 8
// baseline (speedup 1.0000x reference)
#include <cuda_runtime.h>
#include <cstdint>

// Problem constants
#define S_LEN   64
#define D_MODEL 768
#define D_FFN   3072
#define RANK    16
#define MOD_SCALE 0.1f

// Packed f32x2 ops (ptxas won't auto-fuse from C++).
#define FMA_F32X2(d, a, b, c) \
    asm("fma.rn.f32x2 %0, %1, %2, %3;" : "=l"(d) : "l"(a), "l"(b), "l"(c))
// Duplicate a scalar float into a packed {s,s} 64-bit operand.
#define DUP_F32X2(d, s) \
    asm("mov.b64 %0, {%1, %1};" : "=l"(d) : "r"(__float_as_uint(s)))

// Scratch: modulation (64 x 16) + work-stealing counter. Device globals.
__device__ float g_mod[S_LEN * RANK];
__device__ unsigned int g_ctr;

// ---------------------------------------------------------------------------
// Kernel 1: modulation[s][r] = 0.1 * tanh( sum_d attn[s][d] * A[d][r] )
// Warp-per-output: 1024 (s,r) outputs = 128 blocks x 8 warps. Lane l sums
// d = l, l+32, ... (24 elements), then shfl-down tree reduce.
// Also resets the work-stealing counter for the next deltaw launch.
// ---------------------------------------------------------------------------
__global__ __launch_bounds__(256)
void mod_kernel(const float* __restrict__ attn,
                const float* __restrict__ A)
{
    if (blockIdx.x == 0 && threadIdx.x == 0) g_ctr = 0u;

    const int gw  = blockIdx.x * 8 + (threadIdx.x >> 5);  // 0..1023
    const int lid = threadIdx.x & 31;
    const int s   = gw >> 4;
    const int r   = gw & 15;

    const float* arow = attn + (size_t)s * D_MODEL;
    float acc = 0.0f;
#pragma unroll
    for (int k = 0; k < D_MODEL / 32; k++) {       // 24 iterations
        const int d = lid + 32 * k;
        acc += arow[d] * A[d * RANK + r];
    }
#pragma unroll
    for (int off = 16; off > 0; off >>= 1)
        acc += __shfl_down_sync(0xFFFFFFFFu, acc, off);

    if (lid == 0) g_mod[s * RANK + r] = MOD_SCALE * tanhf(acc);
}

// ---------------------------------------------------------------------------
// Kernel 2: delta_w[p][f] = sum_r C[p][r] * B[r][f],  p = s*768 + d,
//           C[p][r] = mod[s][r] * A[d][r]
//
// Persistent work-stealing (444 blocks = 3 CTAs/SM), R7 math core
// (non-dup C smem, mov.b64 dup, 2-chain packed FFMA2, streaming STG.128),
// plus a cross-pair prefetch: next pair's first C quad is loaded during the
// current pair's compute (Cs has a pad row so the last read is in-bounds).
// ---------------------------------------------------------------------------
#define FTILE        1024
#define PAIRS_PER_CH 64
#define THREADS      256
#define N_PCHUNK     ((S_LEN * D_MODEL) / PAIRS_PER_CH)   // 768
#define N_ITEMS      (N_PCHUNK * (D_FFN / FTILE))         // 2304
#define GRID_BLOCKS  444

__global__ __launch_bounds__(THREADS, 3)
void deltaw_kernel(const float* __restrict__ A,
                   const float* __restrict__ B,
                   float* __restrict__ out)
{
    __shared__ float    Cs[PAIRS_PER_CH + 1][RANK];   // +1 pad row (prefetch)
    __shared__ unsigned s_claim;

    ulonglong2 Breg[RANK];
    int prev_ftile = -1;

    for (;;) {
        // Claim next work item; barrier also fences prior compute vs Cs reuse.
        __syncthreads();
        if (threadIdx.x == 0) s_claim = atomicAdd(&g_ctr, 1u);
        __syncthreads();
        const unsigned idx = s_claim;
        if (idx >= N_ITEMS) break;

        const int ftile = (int)(idx / N_PCHUNK);          // 0..2
        const int pair0 = (int)(idx % N_PCHUNK) * PAIRS_PER_CH;
        const int f0    = ftile * FTILE + threadIdx.x * 4;

        // Reload B slab only when the f-tile changes.
        if (ftile != prev_ftile) {
            prev_ftile = ftile;
#pragma unroll
            for (int r = 0; r < RANK; r++) {
                Breg[r] = *reinterpret_cast<const ulonglong2*>(&B[r * D_FFN + f0]);
            }
        }

        // Build C (non-duplicated) for this chunk.
        for (int i = threadIdx.x; i < PAIRS_PER_CH * RANK; i += THREADS) {
            const int p  = i >> 4;
            const int r  = i & 15;
            const int pd = pair0 + p;
            const int s  = pd / D_MODEL;
            const int d  = pd % D_MODEL;
            Cs[p][r] = g_mod[s * RANK + r] * A[d * RANK + r];
        }
        __syncthreads();

        float* outp = out + (size_t)pair0 * D_FFN + f0;
        float4 c0 = *reinterpret_cast<const float4*>(&Cs[0][0]);  // quad 0 prefetch
#pragma unroll 1
        for (int p = 0; p < PAIRS_PER_CH; p++) {
            const float4* cp = reinterpret_cast<const float4*>(&Cs[p][0]);
            const float4 c1 = cp[1];
            const float4 c2 = cp[2];
            const float4 c3 = cp[3];
            // Prefetch next pair's first quad (pad row keeps this in-bounds).
            const float4 c0n = *reinterpret_cast<const float4*>(&Cs[p + 1][0]);

            uint64_t a0 = 0ull;   // packed accum for {f0, f0+1}
            uint64_t a1 = 0ull;   // packed accum for {f0+2, f0+3}
            uint64_t t0, t1, t2, t3;

            DUP_F32X2(t0, c0.x); DUP_F32X2(t1, c0.y);
            DUP_F32X2(t2, c0.z); DUP_F32X2(t3, c0.w);
            FMA_F32X2(a0, t0, Breg[0].x, a0);  FMA_F32X2(a1, t0, Breg[0].y, a1);
            FMA_F32X2(a0, t1, Breg[1].x, a0);  FMA_F32X2(a1, t1, Breg[1].y, a1);
            FMA_F32X2(a0, t2, Breg[2].x, a0);  FMA_F32X2(a1, t2, Breg[2].y, a1);
            FMA_F32X2(a0, t3, Breg[3].x, a0);  FMA_F32X2(a1, t3, Breg[3].y, a1);

            DUP_F32X2(t0, c1.x); DUP_F32X2(t1, c1.y);
            DUP_F32X2(t2, c1.z); DUP_F32X2(t3, c1.w);
            FMA_F32X2(a0, t0, Breg[4].x, a0);  FMA_F32X2(a1, t0, Breg[4].y, a1);
            FMA_F32X2(a0, t1, Breg[5].x, a0);  FMA_F32X2(a1, t1, Breg[5].y, a1);
            FMA_F32X2(a0, t2, Breg[6].x, a0);  FMA_F32X2(a1, t2, Breg[6].y, a1);
            FMA_F32X2(a0, t3, Breg[7].x, a0);  FMA_F32X2(a1, t3, Breg[7].y, a1);

            DUP_F32X2(t0, c2.x); DUP_F32X2(t1, c2.y);
            DUP_F32X2(t2, c2.z); DUP_F32X2(t3, c2.w);
            FMA_F32X2(a0, t0, Breg[8].x, a0);  FMA_F32X2(a1, t0, Breg[8].y, a1);
            FMA_F32X2(a0, t1, Breg[9].x, a0);  FMA_F32X2(a1, t1, Breg[9].y, a1);
            FMA_F32X2(a0, t2, Breg[10].x, a0); FMA_F32X2(a1, t2, Breg[10].y, a1);
            FMA_F32X2(a0, t3, Breg[11].x, a0); FMA_F32X2(a1, t3, Breg[11].y, a1);

            DUP_F32X2(t0, c3.x); DUP_F32X2(t1, c3.y);
            DUP_F32X2(t2, c3.z); DUP_F32X2(t3, c3.w);
            FMA_F32X2(a0, t0, Breg[12].x, a0); FMA_F32X2(a1, t0, Breg[12].y, a1);
            FMA_F32X2(a0, t1, Breg[13].x, a0); FMA_F32X2(a1, t1, Breg[13].y, a1);
            FMA_F32X2(a0, t2, Breg[14].x, a0); FMA_F32X2(a1, t2, Breg[14].y, a1);
            FMA_F32X2(a0, t3, Breg[15].x, a0); FMA_F32X2(a1, t3, Breg[15].y, a1);

            float4 v;
            v.x = __uint_as_float((uint32_t)(a0 & 0xFFFFFFFFull));
            v.y = __uint_as_float((uint32_t)(a0 >> 32));
            v.z = __uint_as_float((uint32_t)(a1 & 0xFFFFFFFFull));
            v.w = __uint_as_float((uint32_t)(a1 >> 32));
            __stcs(reinterpret_cast<float4*>(outp), v);   // streaming store
            outp += D_FFN;

            c0 = c0n;   // rotate prefetched quad into place
        }
    }
}

// ---------------------------------------------------------------------------
// Launch
// ---------------------------------------------------------------------------
extern "C" void kernel_launch(void* const* d_in, const int* in_sizes, int n_in,
                              void* d_out, int out_size)
{
    const float* attn = (const float*)d_in[0];  // (1, 64, 768)
    const float* A    = (const float*)d_in[1];  // (768, 16)
    const float* B    = (const float*)d_in[2];  // (16, 3072)
    float* out        = (float*)d_out;          // (1, 64, 768, 3072)

    mod_kernel<<<128, 256>>>(attn, A);
    deltaw_kernel<<<GRID_BLOCKS, THREADS>>>(A, B, out);
}

// round 9
// speedup vs baseline: 1.0450x; 1.0450x over previous
#include <cuda_runtime.h>
#include <cstdint>

// Problem constants
#define S_LEN   64
#define D_MODEL 768
#define D_FFN   3072
#define RANK    16
#define MOD_SCALE 0.1f

// Packed f32x2 ops (ptxas won't auto-fuse from C++).
#define FMA_F32X2(d, a, b, c) \
    asm("fma.rn.f32x2 %0, %1, %2, %3;" : "=l"(d) : "l"(a), "l"(b), "l"(c))
// Duplicate a scalar float into a packed {s,s} 64-bit operand.
#define DUP_F32X2(d, s) \
    asm("mov.b64 %0, {%1, %1};" : "=l"(d) : "r"(__float_as_uint(s)))

// Scratch: modulation (64 x 16) + work-stealing counter. Device globals.
__device__ float g_mod[S_LEN * RANK];
__device__ unsigned int g_ctr;

// ---------------------------------------------------------------------------
// Kernel 1: modulation[s][r] = 0.1 * tanh( sum_d attn[s][d] * A[d][r] )
// Warp-per-output (R8 version, measured 2.7us incl. launch gap).
// Also resets the work-stealing counter for the deltaw launch that follows.
// ---------------------------------------------------------------------------
__global__ __launch_bounds__(256)
void mod_kernel(const float* __restrict__ attn,
                const float* __restrict__ A)
{
    if (blockIdx.x == 0 && threadIdx.x == 0) g_ctr = 0u;

    const int gw  = blockIdx.x * 8 + (threadIdx.x >> 5);  // 0..1023
    const int lid = threadIdx.x & 31;
    const int s   = gw >> 4;
    const int r   = gw & 15;

    const float* arow = attn + (size_t)s * D_MODEL;
    float acc = 0.0f;
#pragma unroll
    for (int k = 0; k < D_MODEL / 32; k++) {       // 24 iterations
        const int d = lid + 32 * k;
        acc += arow[d] * A[d * RANK + r];
    }
#pragma unroll
    for (int off = 16; off > 0; off >>= 1)
        acc += __shfl_down_sync(0xFFFFFFFFu, acc, off);

    if (lid == 0) g_mod[s * RANK + r] = MOD_SCALE * tanhf(acc);
}

// ---------------------------------------------------------------------------
// Kernel 2: delta_w[p][f] = sum_r C[p][r] * B[r][f],  p = s*768 + d,
//           C[p][r] = mod[s][r] * A[d][r]
//
// R7 core exactly (persistent 444 blocks, non-dup C smem, mov.b64 dup,
// 2-chain packed FFMA2, streaming STG.128) + CLAIM-AHEAD: the atomicAdd for
// the next chunk is issued at the top of the current chunk and its result
// published to smem after the compute loop, so the ~318-cycle global-atomic
// latency is hidden under compute instead of sitting between two barriers.
// ---------------------------------------------------------------------------
#define FTILE        1024
#define PAIRS_PER_CH 64
#define THREADS      256
#define N_PCHUNK     ((S_LEN * D_MODEL) / PAIRS_PER_CH)   // 768
#define N_ITEMS      (N_PCHUNK * (D_FFN / FTILE))         // 2304
#define GRID_BLOCKS  444

__global__ __launch_bounds__(THREADS, 3)
void deltaw_kernel(const float* __restrict__ A,
                   const float* __restrict__ B,
                   float* __restrict__ out)
{
    __shared__ float    Cs[PAIRS_PER_CH][RANK];
    __shared__ unsigned s_claim;

    ulonglong2 Breg[RANK];
    int prev_ftile = -1;

    // Prologue: claim the first work item.
    if (threadIdx.x == 0) s_claim = atomicAdd(&g_ctr, 1u);
    __syncthreads();

    for (;;) {
        const unsigned idx = s_claim;
        if (idx >= N_ITEMS) break;

        // Claim-ahead: start the next atomic now; publish after compute.
        unsigned next_claim = 0u;
        if (threadIdx.x == 0) next_claim = atomicAdd(&g_ctr, 1u);

        const int ftile = (int)(idx / N_PCHUNK);          // 0..2
        const int pair0 = (int)(idx % N_PCHUNK) * PAIRS_PER_CH;
        const int f0    = ftile * FTILE + threadIdx.x * 4;

        // Reload B slab only when the f-tile changes.
        if (ftile != prev_ftile) {
            prev_ftile = ftile;
#pragma unroll
            for (int r = 0; r < RANK; r++) {
                Breg[r] = *reinterpret_cast<const ulonglong2*>(&B[r * D_FFN + f0]);
            }
        }

        // Build C (non-duplicated) for this chunk.
        for (int i = threadIdx.x; i < PAIRS_PER_CH * RANK; i += THREADS) {
            const int p  = i >> 4;
            const int r  = i & 15;
            const int pd = pair0 + p;
            const int s  = pd / D_MODEL;
            const int d  = pd % D_MODEL;
            Cs[p][r] = g_mod[s * RANK + r] * A[d * RANK + r];
        }
        __syncthreads();

        float* outp = out + (size_t)pair0 * D_FFN + f0;
#pragma unroll 1
        for (int p = 0; p < PAIRS_PER_CH; p++) {
            const float4* cp = reinterpret_cast<const float4*>(&Cs[p][0]);
            uint64_t a0 = 0ull;   // packed accum for {f0, f0+1}
            uint64_t a1 = 0ull;   // packed accum for {f0+2, f0+3}
#pragma unroll
            for (int i = 0; i < 4; i++) {
                const float4 c4 = cp[i];      // one broadcast LDS.128
                uint64_t d0, d1, d2, d3;
                DUP_F32X2(d0, c4.x);
                DUP_F32X2(d1, c4.y);
                DUP_F32X2(d2, c4.z);
                DUP_F32X2(d3, c4.w);
                FMA_F32X2(a0, d0, Breg[4 * i + 0].x, a0);
                FMA_F32X2(a1, d0, Breg[4 * i + 0].y, a1);
                FMA_F32X2(a0, d1, Breg[4 * i + 1].x, a0);
                FMA_F32X2(a1, d1, Breg[4 * i + 1].y, a1);
                FMA_F32X2(a0, d2, Breg[4 * i + 2].x, a0);
                FMA_F32X2(a1, d2, Breg[4 * i + 2].y, a1);
                FMA_F32X2(a0, d3, Breg[4 * i + 3].x, a0);
                FMA_F32X2(a1, d3, Breg[4 * i + 3].y, a1);
            }
            float4 v;
            v.x = __uint_as_float((uint32_t)(a0 & 0xFFFFFFFFull));
            v.y = __uint_as_float((uint32_t)(a0 >> 32));
            v.z = __uint_as_float((uint32_t)(a1 & 0xFFFFFFFFull));
            v.w = __uint_as_float((uint32_t)(a1 >> 32));
            __stcs(reinterpret_cast<float4*>(outp), v);   // streaming store
            outp += D_FFN;
        }

        // Publish the prefetched claim; barrier orders it and the Cs reuse.
        if (threadIdx.x == 0) s_claim = next_claim;
        __syncthreads();
    }
}

// ---------------------------------------------------------------------------
// Launch
// ---------------------------------------------------------------------------
extern "C" void kernel_launch(void* const* d_in, const int* in_sizes, int n_in,
                              void* d_out, int out_size)
{
    const float* attn = (const float*)d_in[0];  // (1, 64, 768)
    const float* A    = (const float*)d_in[1];  // (768, 16)
    const float* B    = (const float*)d_in[2];  // (16, 3072)
    float* out        = (float*)d_out;          // (1, 64, 768, 3072)

    mod_kernel<<<128, 256>>>(attn, A);
    deltaw_kernel<<<GRID_BLOCKS, THREADS>>>(A, B, out);
}